// round 9
// baseline (speedup 1.0000x reference)
#include <cuda_runtime.h>
#include <cuda_bf16.h>
#include <cuda_fp16.h>
#include <cstdint>
#include <math.h>

#define Nn 65536
#define Kc 8
#define Hs 128
#define Tt 4
#define APAD 136          // padded row stride in 16-bit elems (272B: conflict-free ldmatrix)

// ---------------------------------------------------------------------------
// Device scratch (allocation-free rule: __device__ globals)
// ---------------------------------------------------------------------------
__device__ int   g_cnt[Tt];
__device__ int   g_perm[Tt][Nn];
__device__ float g_hsum[(size_t)Nn * Hs];
__device__ __align__(16) __half        g_Bf[Tt][Hs * Hs];        // fp16 U_f
__device__ __align__(16) __nv_bfloat16 g_Bi[2][Tt][3][Hs * Hs];  // bf16 hi/lo U_iou

// ---------------------------------------------------------------------------
// Warp-MMA helpers (sm_80-class: valid on plain sm_103 target)
// ---------------------------------------------------------------------------
__device__ __forceinline__ uint32_t smem_to_u32(const void* p) {
    uint32_t a;
    asm("{ .reg .u64 t; cvta.to.shared.u64 t, %1; cvt.u32.u64 %0, t; }" : "=r"(a) : "l"(p));
    return a;
}
__device__ __forceinline__ void ldm_x4(uint32_t* r, uint32_t a) {
    asm volatile("ldmatrix.sync.aligned.m8n8.x4.shared.b16 {%0,%1,%2,%3}, [%4];"
        : "=r"(r[0]), "=r"(r[1]), "=r"(r[2]), "=r"(r[3]) : "r"(a));
}
__device__ __forceinline__ void ldm_x4t(uint32_t* r, uint32_t a) {
    asm volatile("ldmatrix.sync.aligned.m8n8.x4.trans.shared.b16 {%0,%1,%2,%3}, [%4];"
        : "=r"(r[0]), "=r"(r[1]), "=r"(r[2]), "=r"(r[3]) : "r"(a));
}
__device__ __forceinline__ void mma16816bf(float* c, const uint32_t* a, const uint32_t* b) {
    asm volatile("mma.sync.aligned.m16n8k16.row.col.f32.bf16.bf16.f32 "
        "{%0,%1,%2,%3}, {%4,%5,%6,%7}, {%8,%9}, {%0,%1,%2,%3};"
        : "+f"(c[0]), "+f"(c[1]), "+f"(c[2]), "+f"(c[3])
        : "r"(a[0]), "r"(a[1]), "r"(a[2]), "r"(a[3]), "r"(b[0]), "r"(b[1]));
}
__device__ __forceinline__ void mma16816h(float* c, const uint32_t* a, const uint32_t* b) {
    asm volatile("mma.sync.aligned.m16n8k16.row.col.f32.f16.f16.f32 "
        "{%0,%1,%2,%3}, {%4,%5,%6,%7}, {%8,%9}, {%0,%1,%2,%3};"
        : "+f"(c[0]), "+f"(c[1]), "+f"(c[2]), "+f"(c[3])
        : "r"(a[0]), "r"(a[1]), "r"(a[2]), "r"(a[3]), "r"(b[0]), "r"(b[1]));
}
__device__ __forceinline__ void bf16_split2(float x, float y,
                                            __nv_bfloat162& hi, __nv_bfloat162& lo) {
    hi = __floats2bfloat162_rn(x, y);
    lo = __floats2bfloat162_rn(x - __bfloat162float(hi.x), y - __bfloat162float(hi.y));
}

// ---------------------------------------------------------------------------
// Bucket nodes by type
// ---------------------------------------------------------------------------
__global__ void k_zero() { if (threadIdx.x < Tt) g_cnt[threadIdx.x] = 0; }

__global__ void __launch_bounds__(256) k_bucket(const int* __restrict__ type_id) {
    __shared__ int scnt[Tt];
    __shared__ int sbase[Tt];
    const int tid = threadIdx.x;
    if (tid < Tt) scnt[tid] = 0;
    __syncthreads();
    const int n = blockIdx.x * 256 + tid;
    const int t = type_id[n];
    const int local = atomicAdd(&scnt[t], 1);
    __syncthreads();
    if (tid < Tt) sbase[tid] = atomicAdd(&g_cnt[tid], scnt[tid]);
    __syncthreads();
    g_perm[t][sbase[t] + local] = n;
}

// ---------------------------------------------------------------------------
// Weight prep: fp16 U_f; bf16 hi/lo U_iou (row-major [i][j])
// ---------------------------------------------------------------------------
__global__ void __launch_bounds__(256) k_prepw(const float* __restrict__ U_iou,
                                               const float* __restrict__ U_f) {
    int idx = blockIdx.x * 256 + threadIdx.x;     // 262144
    int t   = idx >> 16;
    int rem = idx & 65535;
    int m   = rem >> 14;                          // 0 = f, 1..3 = iou jtile
    int i   = (rem >> 7) & 127;
    int j   = rem & 127;
    int e   = i * Hs + j;
    if (m == 0) {
        g_Bf[t][e] = __float2half(U_f[((size_t)t * Hs + i) * Hs + j]);
    } else {
        float v = U_iou[((size_t)t * Hs + i) * 3 * Hs + (m - 1) * Hs + j];
        __nv_bfloat16 hi = __float2bfloat16(v);
        __nv_bfloat16 lo = __float2bfloat16(v - __bfloat162float(hi));
        g_Bi[0][t][m - 1][e] = hi; g_Bi[1][t][m - 1][e] = lo;
    }
}

// ---------------------------------------------------------------------------
// k_fmma: PERSISTENT, 4 CTAs/SM. grid = 4 types x 148 slots. B_f[t] fp16
// resident in smem; CTA strides over 8-node tiles (M=64, K=128, N=128,
// single-pass fp16). A single-buffered (two syncs/tile); epilogue does
// sigmoid(D+f_input+b_f)*c and reduces over the 8 children via shfl.bfly.
// smem: B[128][136] fp16 (34816) | A[64][136] fp16 (17408)  = 52224
// ---------------------------------------------------------------------------
#define FSLOTS 148
__global__ void __launch_bounds__(256, 4) k_fmma(
    const float* __restrict__ h, const float* __restrict__ c_in,
    const float* __restrict__ f_input, const float* __restrict__ b_f,
    float* __restrict__ out)
{
    const int t    = blockIdx.x & 3;
    const int slot = blockIdx.x >> 2;
    const int cnt  = g_cnt[t];
    const int ntiles = (cnt + 7) >> 3;

    extern __shared__ __align__(16) char sm[];
    __half* Bf = (__half*)sm;                       // 34816
    __half* Af = (__half*)(sm + 34816);             // 17408
    const uint32_t su = smem_to_u32(sm);
    const uint32_t bOff = su, aOff = su + 34816;

    const int tid  = threadIdx.x;
    const int wid  = tid >> 5, lane = tid & 31;
    const int wm = wid & 1, wn = wid >> 1;
    const int l15 = lane & 15, lh = (lane >> 4) << 3;
    const int q = lane & 3, lr = lane >> 2;
    const int* perm = g_perm[t];

    // ---- B load once (L2-hot), padded ----
    {
        const uint4* sh = (const uint4*)g_Bf[t];
        #pragma unroll
        for (int i = tid; i < 2048; i += 256) {
            int row = i >> 4, qq = i & 15;
            *(uint4*)(Bf + row * APAD + qq * 8) = sh[i];
        }
    }

    const int cp  = (tid & 63) * 2;
    const int grp = tid >> 6;

    for (int tile = slot; tile < ntiles; tile += FSLOTS) {
        // ---- gather: h -> fp16 smem, fused h_sum -> global ----
        #pragma unroll
        for (int nn = 0; nn < 2; nn++) {
            const int nl = grp * 2 + nn;
            const int n  = perm[min(tile * 8 + nl, cnt - 1)];
            const size_t nb = (size_t)n * (Kc * Hs);
            float hx = 0.f, hy = 0.f;
            #pragma unroll
            for (int k = 0; k < Kc; k++) {
                float2 v = *(const float2*)(h + nb + k * Hs + cp);
                hx += v.x; hy += v.y;
                *(__half2*)(Af + (nl * 8 + k) * APAD + cp) = __floats2half2_rn(v.x, v.y);
            }
            *(float2*)(g_hsum + (size_t)n * Hs + cp) = make_float2(hx, hy);
        }
        __syncthreads();   // gather visible (covers B on first tile)

        // ---- single-pass fp16 MMA ----
        float acc[2][4][4];
        #pragma unroll
        for (int mt = 0; mt < 2; mt++)
            #pragma unroll
            for (int nt = 0; nt < 4; nt++)
                #pragma unroll
                for (int e = 0; e < 4; e++) acc[mt][nt][e] = 0.f;

        #pragma unroll
        for (int ks = 0; ks < 8; ks++) {
            uint32_t a[2][4];
            #pragma unroll
            for (int mt = 0; mt < 2; mt++)
                ldm_x4(a[mt], aOff + (((wm * 32 + mt * 16 + l15) * APAD + ks * 16 + lh) << 1));
            uint32_t b[4][2];
            #pragma unroll
            for (int nb2 = 0; nb2 < 2; nb2++) {
                uint32_t r[4];
                ldm_x4t(r, bOff + (((ks * 16 + l15) * APAD + wn * 32 + nb2 * 16 + lh) << 1));
                b[nb2 * 2][0] = r[0]; b[nb2 * 2][1] = r[1];
                b[nb2 * 2 + 1][0] = r[2]; b[nb2 * 2 + 1][1] = r[3];
            }
            #pragma unroll
            for (int mt = 0; mt < 2; mt++)
                #pragma unroll
                for (int nt = 0; nt < 4; nt++)
                    mma16816h(acc[mt][nt], a[mt], b[nt]);
        }
        __syncthreads();   // all warps done reading A before next gather

        // ---- epilogue: sigmoid(D + f_input + b_f) * c, shfl k-reduction ----
        #pragma unroll
        for (int mt = 0; mt < 2; mt++) {
            const int na_l = wm * 4 + mt * 2;          // local nodes na_l, na_l+1
            const int na = perm[min(tile * 8 + na_l, cnt - 1)];
            const int nb = perm[min(tile * 8 + na_l + 1, cnt - 1)];
            const float* fa = f_input + (size_t)na * Hs;
            const float* fb = f_input + (size_t)nb * Hs;
            const float* ca = c_in + (size_t)na * (Kc * Hs) + lr * Hs;
            const float* cb = c_in + (size_t)nb * (Kc * Hs) + lr * Hs;
            #pragma unroll
            for (int nt = 0; nt < 4; nt++) {
                const int col = wn * 32 + nt * 8 + q * 2;
                float2 bfv = *(const float2*)(b_f + t * Hs + col);   // L1-hot
                float2 f2a = *(const float2*)(fa + col);
                float2 f2b = *(const float2*)(fb + col);
                float2 c2a = *(const float2*)(ca + col);
                float2 c2b = *(const float2*)(cb + col);
                float x0 = acc[mt][nt][0] + f2a.x + bfv.x;
                float x1 = acc[mt][nt][1] + f2a.y + bfv.y;
                float x2 = acc[mt][nt][2] + f2b.x + bfv.x;
                float x3 = acc[mt][nt][3] + f2b.y + bfv.y;
                float v0 = c2a.x / (1.f + __expf(-x0));
                float v1 = c2a.y / (1.f + __expf(-x1));
                float v2 = c2b.x / (1.f + __expf(-x2));
                float v3 = c2b.y / (1.f + __expf(-x3));
                #pragma unroll
                for (int d = 4; d < 32; d <<= 1) {
                    v0 += __shfl_xor_sync(0xFFFFFFFFu, v0, d);
                    v1 += __shfl_xor_sync(0xFFFFFFFFu, v1, d);
                    v2 += __shfl_xor_sync(0xFFFFFFFFu, v2, d);
                    v3 += __shfl_xor_sync(0xFFFFFFFFu, v3, d);
                }
                if (lr == 0) {
                    if (tile * 8 + na_l < cnt)
                        *(float2*)(out + (size_t)na * (4 * Hs) + 3 * Hs + col) = make_float2(v0, v1);
                    if (tile * 8 + na_l + 1 < cnt)
                        *(float2*)(out + (size_t)nb * (4 * Hs) + 3 * Hs + col) = make_float2(v2, v3);
                }
            }
        }
    }
}

// ---------------------------------------------------------------------------
// k_imma: PERSISTENT per (type, jtile). grid = 12 groups x 25 slots.
// B_iou[t][jt] hi/lo resident in smem; CTA strides over 64-node tiles
// (M=64, K=128, N=128, 3-pass bf16-split). Direct register epilogue.
// smem: Ah|Al (34816) | Bh|Bl (69632)
// ---------------------------------------------------------------------------
#define ISLOTS 25
__global__ void __launch_bounds__(256, 2) k_imma(
    const float* __restrict__ b_iou, float* __restrict__ out)
{
    const int grpid = blockIdx.x % 12;
    const int slot  = blockIdx.x / 12;
    const int t  = grpid & 3;
    const int jt = grpid >> 2;          // 0..2
    const int cnt = g_cnt[t];
    const int ntiles = (cnt + 63) >> 6;

    extern __shared__ __align__(16) char sm[];
    __nv_bfloat16* Ah = (__nv_bfloat16*)sm;
    __nv_bfloat16* Al = Ah + 64 * APAD;
    __nv_bfloat16* Bh = Al + 64 * APAD;
    __nv_bfloat16* Bl = Bh + Hs * APAD;
    const uint32_t su = smem_to_u32(sm);
    const uint32_t aHi = su, aLo = su + 17408, bHi = su + 34816, bLo = su + 69632;

    const int tid = threadIdx.x;
    const int wid = tid >> 5, lane = tid & 31;
    const int wm = wid & 1, wn = wid >> 1;
    const int l15 = lane & 15, lh = (lane >> 4) << 3;
    const int q = lane & 3, lr = lane >> 2;
    const int* perm = g_perm[t];

    // ---- B load once ----
    {
        const uint4* sh = (const uint4*)g_Bi[0][t][jt];
        const uint4* sl = (const uint4*)g_Bi[1][t][jt];
        #pragma unroll
        for (int i = tid; i < 2048; i += 256) {
            int row = i >> 4, qq = i & 15;
            *(uint4*)(Bh + row * APAD + qq * 8) = sh[i];
            *(uint4*)(Bl + row * APAD + qq * 8) = sl[i];
        }
    }
    float2 bv[4];
    #pragma unroll
    for (int nt = 0; nt < 4; nt++)
        bv[nt] = *(const float2*)(b_iou + (size_t)t * 3 * Hs + jt * Hs + wn * 32 + nt * 8 + q * 2);

    const int cp  = (tid & 63) * 2;
    const int grp = tid >> 6;

    for (int tile = slot; tile < ntiles; tile += ISLOTS) {
        // ---- A gather: split h_sum rows ----
        #pragma unroll 4
        for (int rr = 0; rr < 16; rr++) {
            const int row = grp * 16 + rr;
            const int n = perm[min(tile * 64 + row, cnt - 1)];
            float2 v = *(const float2*)(g_hsum + (size_t)n * Hs + cp);
            __nv_bfloat162 hi2, lo2;
            bf16_split2(v.x, v.y, hi2, lo2);
            *(__nv_bfloat162*)(Ah + row * APAD + cp) = hi2;
            *(__nv_bfloat162*)(Al + row * APAD + cp) = lo2;
        }
        __syncthreads();   // A visible (covers B on first tile)

        float acc[2][4][4];
        #pragma unroll
        for (int mt = 0; mt < 2; mt++)
            #pragma unroll
            for (int nt = 0; nt < 4; nt++)
                #pragma unroll
                for (int e = 0; e < 4; e++) acc[mt][nt][e] = 0.f;

        #pragma unroll
        for (int pass = 0; pass < 3; pass++) {
            const uint32_t Ab = (pass == 2) ? aLo : aHi;
            const uint32_t Bb = (pass == 1) ? bLo : bHi;
            #pragma unroll
            for (int ks = 0; ks < 8; ks++) {
                uint32_t a[2][4];
                #pragma unroll
                for (int mt = 0; mt < 2; mt++)
                    ldm_x4(a[mt], Ab + (((wm * 32 + mt * 16 + l15) * APAD + ks * 16 + lh) << 1));
                uint32_t b[4][2];
                #pragma unroll
                for (int nb2 = 0; nb2 < 2; nb2++) {
                    uint32_t r[4];
                    ldm_x4t(r, Bb + (((ks * 16 + l15) * APAD + wn * 32 + nb2 * 16 + lh) << 1));
                    b[nb2 * 2][0] = r[0]; b[nb2 * 2][1] = r[1];
                    b[nb2 * 2 + 1][0] = r[2]; b[nb2 * 2 + 1][1] = r[3];
                }
                #pragma unroll
                for (int mt = 0; mt < 2; mt++)
                    #pragma unroll
                    for (int nt = 0; nt < 4; nt++)
                        mma16816bf(acc[mt][nt], a[mt], b[nt]);
            }
        }

        // ---- direct epilogue: + b_iou, store ----
        #pragma unroll
        for (int mt = 0; mt < 2; mt++) {
            #pragma unroll
            for (int half = 0; half < 2; half++) {
                const int row = wm * 32 + mt * 16 + lr + half * 8;
                if (tile * 64 + row < cnt) {
                    float* orow = out + (size_t)perm[tile * 64 + row] * (4 * Hs) + jt * Hs;
                    #pragma unroll
                    for (int nt = 0; nt < 4; nt++) {
                        const int col = wn * 32 + nt * 8 + q * 2;
                        *(float2*)(orow + col) = make_float2(
                            acc[mt][nt][half * 2 + 0] + bv[nt].x,
                            acc[mt][nt][half * 2 + 1] + bv[nt].y);
                    }
                }
            }
        }
        __syncthreads();   // MMA/epilogue done before next gather overwrites A
    }
}

// ---------------------------------------------------------------------------
extern "C" void kernel_launch(void* const* d_in, const int* in_sizes, int n_in,
                              void* d_out, int out_size)
{
    const float* h       = (const float*)d_in[0];
    const float* c       = (const float*)d_in[1];
    const float* f_input = (const float*)d_in[2];
    const int*   type_id = (const int*)  d_in[3];
    const float* U_iou   = (const float*)d_in[4];
    const float* b_iou   = (const float*)d_in[5];
    const float* U_f     = (const float*)d_in[6];
    const float* b_f     = (const float*)d_in[7];
    float*       out     = (float*)d_out;

    const int smemF = 34816 + 17408;        // 52224 -> 4 CTAs/SM
    const int smemI = 34816 + 69632;        // 104448 -> 2 CTAs/SM
    cudaFuncSetAttribute(k_fmma, cudaFuncAttributeMaxDynamicSharedMemorySize, smemF);
    cudaFuncSetAttribute(k_imma, cudaFuncAttributeMaxDynamicSharedMemorySize, smemI);

    k_zero<<<1, 32>>>();
    k_bucket<<<Nn / 256, 256>>>(type_id);
    k_prepw<<<1024, 256>>>(U_iou, U_f);

    k_fmma<<<4 * FSLOTS, 256, smemF>>>(h, c, f_input, b_f, out);
    k_imma<<<12 * ISLOTS, 256, smemI>>>(b_iou, out);
}